// round 1
// baseline (speedup 1.0000x reference)
#include <cuda_runtime.h>
#include <cuda_bf16.h>
#include <mma.h>

// Problem constants
#define B_  128
#define S_  256
#define D_  512
#define H_  1024
#define NC_ 128
#define NG  4
#define N4  (NG*H_)   // 4096

// Device scratch (allocation-free rule: __device__ globals)
__device__ float          g_table[129 * N4];          // [c][gate*1024+j] input-side preacts incl bias
__device__ __nv_bfloat16  g_Whb[N4 * H_];             // [n_global][k] = W?h[k][j] transposed, bf16
__device__ float          g_h[B_ * H_];               // fp32 h (last step feeds final proj)
__device__ __nv_bfloat16  g_hb[2][B_ * H_];           // ping-pong bf16 h
__device__ float          g_C[B_ * H_];               // cell state fp32

// ---------------------------------------------------------------------------
// Table: g_table[c][g*1024+j] = sum_d emb[c][d] * Wgx[d][j] + bias_g[j]
// grid (16, 17), block 256. Each thread: one n-column, 8 c's.
// ---------------------------------------------------------------------------
__global__ void k_table(const float* __restrict__ emb,
                        const float* __restrict__ Wfx, const float* __restrict__ Wix,
                        const float* __restrict__ Wgx, const float* __restrict__ Wox,
                        const float* __restrict__ bf,  const float* __restrict__ bi,
                        const float* __restrict__ bg,  const float* __restrict__ bo)
{
    int n    = blockIdx.x * 256 + threadIdx.x;          // 0..4095
    int gate = n >> 10;
    int j    = n & 1023;
    const float* W  = (gate == 0) ? Wfx : (gate == 1) ? Wix : (gate == 2) ? Wgx : Wox;
    const float* bb = (gate == 0) ? bf  : (gate == 1) ? bi  : (gate == 2) ? bg  : bo;
    int c0 = blockIdx.y * 8;

    float acc[8];
#pragma unroll
    for (int cc = 0; cc < 8; cc++) acc[cc] = 0.f;

    for (int d = 0; d < D_; d++) {
        float w = W[d * H_ + j];
#pragma unroll
        for (int cc = 0; cc < 8; cc++) {
            int c = c0 + cc;
            float e = (c < 129) ? emb[c * D_ + d] : 0.f;
            acc[cc] = fmaf(e, w, acc[cc]);
        }
    }
    float bv = bb[j];
#pragma unroll
    for (int cc = 0; cc < 8; cc++) {
        int c = c0 + cc;
        if (c < 129) g_table[c * N4 + n] = acc[cc] + bv;
    }
}

// ---------------------------------------------------------------------------
// Transpose + bf16 convert recurrent weights: g_Whb[(g*1024+n)*1024 + k] = Wgh[k][n]
// grid (32, 32, 4), block (32, 8)
// ---------------------------------------------------------------------------
__global__ void k_convert(const float* __restrict__ W0, const float* __restrict__ W1,
                          const float* __restrict__ W2, const float* __restrict__ W3)
{
    const float* W = (blockIdx.z == 0) ? W0 : (blockIdx.z == 1) ? W1
                   : (blockIdx.z == 2) ? W2 : W3;
    __shared__ float t[32][33];
    int k0 = blockIdx.x * 32;
    int n0 = blockIdx.y * 32;
    int tx = threadIdx.x, ty = threadIdx.y;
#pragma unroll
    for (int i = 0; i < 4; i++)
        t[ty + i * 8][tx] = W[(k0 + ty + i * 8) * H_ + n0 + tx];
    __syncthreads();
    size_t gbase = (size_t)(blockIdx.z * H_ + n0) * H_;
#pragma unroll
    for (int i = 0; i < 4; i++)
        g_Whb[gbase + (size_t)(ty + i * 8) * H_ + k0 + tx] =
            __float2bfloat16(t[tx][ty + i * 8]);
}

// ---------------------------------------------------------------------------
// Zero initial state
// ---------------------------------------------------------------------------
__global__ void k_init()
{
    int idx = blockIdx.x * blockDim.x + threadIdx.x;
    if (idx < B_ * H_) {
        g_C[idx]      = 0.f;
        g_hb[0][idx]  = __float2bfloat16(0.f);
    }
}

// ---------------------------------------------------------------------------
// One recurrent step: z = table[x[:,s]] + h @ Wh (bf16 WMMA, fp32 accum),
// then gates + C/h update fused in epilogue.
// Block tile: 64 batch rows x (4 gates x 16 j) = 64x64 GEMM tile.
// grid (2, 64), 256 threads (8 warps: 4 m x 2 n-halves).
// ---------------------------------------------------------------------------
__global__ void __launch_bounds__(256)
k_step(const int* __restrict__ x, int s)
{
    using namespace nvcuda::wmma;
    const int mb  = blockIdx.x * 64;     // batch offset
    const int jb  = blockIdx.y * 16;     // j offset (within each gate)
    const int buf = s & 1;
    const __nv_bfloat16* hb = g_hb[buf];

    const int wid = threadIdx.x >> 5;
    const int wm  = wid >> 1;            // 0..3  (16 batch rows each)
    const int wn  = wid & 1;             // 0..1  (2 gates each)

    fragment<accumulator, 16, 16, 16, float> acc0, acc1;
    fill_fragment(acc0, 0.f);
    fill_fragment(acc1, 0.f);
    fragment<matrix_a, 16, 16, 16, __nv_bfloat16, row_major> fa;
    fragment<matrix_b, 16, 16, 16, __nv_bfloat16, col_major> fb0, fb1;

    const __nv_bfloat16* Aptr = hb + (size_t)(mb + wm * 16) * H_;
    const __nv_bfloat16* B0   = g_Whb + (size_t)((wn * 2 + 0) * H_ + jb) * H_;
    const __nv_bfloat16* B1   = g_Whb + (size_t)((wn * 2 + 1) * H_ + jb) * H_;

#pragma unroll 4
    for (int k = 0; k < H_; k += 16) {
        load_matrix_sync(fa,  Aptr + k, H_);
        load_matrix_sync(fb0, B0 + k,  H_);
        load_matrix_sync(fb1, B1 + k,  H_);
        mma_sync(acc0, fa, fb0, acc0);
        mma_sync(acc1, fa, fb1, acc1);
    }

    __shared__ float zs[64][68];
    store_matrix_sync(&zs[wm * 16][(wn * 2 + 0) * 16], acc0, 68, mem_row_major);
    store_matrix_sync(&zs[wm * 16][(wn * 2 + 1) * 16], acc1, 68, mem_row_major);
    __syncthreads();

    // Epilogue: 64 m x 16 j pairs, 4 per thread
    for (int p = threadIdx.x; p < 64 * 16; p += 256) {
        int m  = p >> 4;
        int jj = p & 15;
        int b  = mb + m;
        int j  = jb + jj;
        int c  = x[b * S_ + s];                 // x[b][s][0]
        float r = (c > 0) ? 1.f : 0.f;
        const float* tb = g_table + (size_t)c * N4 + j;
        float zf = zs[m][ 0 + jj] + tb[0];
        float zi = zs[m][16 + jj] + tb[1024];
        float zg = zs[m][32 + jj] + tb[2048];
        float zo = zs[m][48 + jj] + tb[3072];
        float fg = 1.f / (1.f + __expf(-zf));
        float ig = 1.f / (1.f + __expf(-zi));
        float gg = 1.f / (1.f + __expf(-zg));   // sigmoid, as in reference
        float og = 1.f / (1.f + __expf(-zo));
        int idx = b * H_ + j;
        float C = (gg * ig + g_C[idx] * fg) * r;
        g_C[idx] = C;
        float h = og * tanhf(C);
        g_h[idx] = h;
        g_hb[buf ^ 1][idx] = __float2bfloat16(h);
    }
}

// ---------------------------------------------------------------------------
// Final projection + log_softmax. grid 128 (one block per batch row), 128 threads.
// ---------------------------------------------------------------------------
__global__ void k_final(const float* __restrict__ Wph, const float* __restrict__ bp,
                        float* __restrict__ out)
{
    int b = blockIdx.x;
    int j = threadIdx.x;
    const float* h = g_h + (size_t)b * H_;
    float acc = bp[j];
    for (int k = 0; k < H_; k++)
        acc = fmaf(h[k], Wph[k * NC_ + j], acc);

    __shared__ float red[NC_];
    red[j] = acc;
    __syncthreads();
    for (int off = 64; off > 0; off >>= 1) {
        if (j < off) red[j] = fmaxf(red[j], red[j + off]);
        __syncthreads();
    }
    float m = red[0];
    __syncthreads();
    red[j] = expf(acc - m);
    __syncthreads();
    for (int off = 64; off > 0; off >>= 1) {
        if (j < off) red[j] += red[j + off];
        __syncthreads();
    }
    float lse = m + logf(red[0]);
    out[b * NC_ + j] = acc - lse;
}

// ---------------------------------------------------------------------------
// Inputs (metadata order):
// 0 x(int32)  1 emb  2 Wfx 3 Wfh 4 bf  5 Wix 6 Wih 7 bi
// 8 Wgx 9 Wgh 10 bg  11 Wox 12 Woh 13 bo  14 Wph 15 bp
// ---------------------------------------------------------------------------
extern "C" void kernel_launch(void* const* d_in, const int* in_sizes, int n_in,
                              void* d_out, int out_size)
{
    const int*   x   = (const int*)  d_in[0];
    const float* emb = (const float*)d_in[1];
    const float* Wfx = (const float*)d_in[2];
    const float* Wfh = (const float*)d_in[3];
    const float* bf  = (const float*)d_in[4];
    const float* Wix = (const float*)d_in[5];
    const float* Wih = (const float*)d_in[6];
    const float* bi  = (const float*)d_in[7];
    const float* Wgx = (const float*)d_in[8];
    const float* Wgh = (const float*)d_in[9];
    const float* bg  = (const float*)d_in[10];
    const float* Wox = (const float*)d_in[11];
    const float* Woh = (const float*)d_in[12];
    const float* bo  = (const float*)d_in[13];
    const float* Wph = (const float*)d_in[14];
    const float* bp  = (const float*)d_in[15];
    float* out = (float*)d_out;

    k_table<<<dim3(16, 17), 256>>>(emb, Wfx, Wix, Wgx, Wox, bf, bi, bg, bo);
    k_convert<<<dim3(32, 32, 4), dim3(32, 8)>>>(Wfh, Wih, Wgh, Woh);
    k_init<<<(B_ * H_ + 255) / 256, 256>>>();

    for (int s = 0; s < S_; s++)
        k_step<<<dim3(2, 64), 256>>>(x, s);

    k_final<<<NC_, NC_>>>(Wph, bp, out);
}

// round 4
// speedup vs baseline: 2.8377x; 2.8377x over previous
#include <cuda_runtime.h>
#include <cuda_bf16.h>
#include <mma.h>
#include <cstdint>

// Problem constants
#define B_  128
#define S_  256
#define D_  512
#define H_  1024
#define NC_ 128
#define N4  4096

#define NBLK      128
#define WS_STRIDE 1032      // bf16 elems per weight row (516 words == 4 mod 32 -> conflict-free ldmatrix)
#define AS_STRIDE 136       // bf16 elems per A row (68 words == 4 mod 32)
#define KC        128       // k-chunk staged per cp.async round

// smem layout (bytes)
#define WS_OFF 0
#define WS_SZ  (64 * WS_STRIDE * 2)            // 132096
#define AS_OFF (WS_OFF + WS_SZ)                // 132096
#define AS_SZ  (2 * 64 * AS_STRIDE * 2)        // 34816
#define ZS_OFF (AS_OFF + AS_SZ)                // 166912
#define ZS_SZ  (64 * 68 * 4)                   // 17408
#define CS_OFF (ZS_OFF + ZS_SZ)                // 184320
#define CS_SZ  (64 * 16 * 4)                   // 4096
#define SMEM_TOTAL (CS_OFF + CS_SZ)            // 188416

// Device scratch
__device__ float          g_table[129 * N4];   // input-side preacts incl bias, per vocab id
__device__ __nv_bfloat16  g_Whb[N4 * H_];      // [n_global][k] = W?h[k][j], bf16
__device__ float          g_h[B_ * H_];        // final-step h (fp32) for projection
__device__ __nv_bfloat16  g_hb[2][B_ * H_];    // ping-pong bf16 h
__device__ unsigned       g_cnt;               // barrier arrive counter (self-resetting)
__device__ volatile unsigned g_gen;            // barrier generation (monotonic, replay-safe)

// ---------------------------------------------------------------------------
// Table: g_table[c][g*1024+j] = sum_d emb[c][d] * Wgx[d][j] + bias_g[j]
// ---------------------------------------------------------------------------
__global__ void k_table(const float* __restrict__ emb,
                        const float* __restrict__ Wfx, const float* __restrict__ Wix,
                        const float* __restrict__ Wgx, const float* __restrict__ Wox,
                        const float* __restrict__ bf,  const float* __restrict__ bi,
                        const float* __restrict__ bg,  const float* __restrict__ bo)
{
    int n    = blockIdx.x * 256 + threadIdx.x;          // 0..4095
    int gate = n >> 10;
    int j    = n & 1023;
    const float* W  = (gate == 0) ? Wfx : (gate == 1) ? Wix : (gate == 2) ? Wgx : Wox;
    const float* bb = (gate == 0) ? bf  : (gate == 1) ? bi  : (gate == 2) ? bg  : bo;
    int c0 = blockIdx.y * 8;

    float acc[8];
#pragma unroll
    for (int cc = 0; cc < 8; cc++) acc[cc] = 0.f;

    for (int d = 0; d < D_; d++) {
        float w = W[d * H_ + j];
#pragma unroll
        for (int cc = 0; cc < 8; cc++) {
            int c = c0 + cc;
            float e = (c < 129) ? emb[c * D_ + d] : 0.f;
            acc[cc] = fmaf(e, w, acc[cc]);
        }
    }
    float bv = bb[j];
#pragma unroll
    for (int cc = 0; cc < 8; cc++) {
        int c = c0 + cc;
        if (c < 129) g_table[c * N4 + n] = acc[cc] + bv;
    }
}

// ---------------------------------------------------------------------------
// Transpose + bf16 convert recurrent weights: g_Whb[(g*1024+n)*1024 + k] = Wgh[k][n]
// ---------------------------------------------------------------------------
__global__ void k_convert(const float* __restrict__ W0, const float* __restrict__ W1,
                          const float* __restrict__ W2, const float* __restrict__ W3)
{
    const float* W = (blockIdx.z == 0) ? W0 : (blockIdx.z == 1) ? W1
                   : (blockIdx.z == 2) ? W2 : W3;
    __shared__ float t[32][33];
    int k0 = blockIdx.x * 32;
    int n0 = blockIdx.y * 32;
    int tx = threadIdx.x, ty = threadIdx.y;
#pragma unroll
    for (int i = 0; i < 4; i++)
        t[ty + i * 8][tx] = W[(k0 + ty + i * 8) * H_ + n0 + tx];
    __syncthreads();
    size_t gbase = (size_t)(blockIdx.z * H_ + n0) * H_;
#pragma unroll
    for (int i = 0; i < 4; i++)
        g_Whb[gbase + (size_t)(ty + i * 8) * H_ + k0 + tx] =
            __float2bfloat16(t[tx][ty + i * 8]);
}

// ---------------------------------------------------------------------------
// Zero initial h (buffer 0)
// ---------------------------------------------------------------------------
__global__ void k_init()
{
    int idx = blockIdx.x * blockDim.x + threadIdx.x;
    if (idx < B_ * H_) g_hb[0][idx] = __float2bfloat16(0.f);
}

// ---------------------------------------------------------------------------
// Grid-wide barrier (all NBLK blocks guaranteed resident: 128 blocks, 1/SM, 148 SMs).
// Generation-based, self-resetting, replay-safe. PTX fences are cumulative, so
// thread-0's __threadfence releases the whole block's stores (ordered by the
// preceding __syncthreads) and acquires peers' stores for the whole block.
// ---------------------------------------------------------------------------
__device__ __forceinline__ void grid_barrier()
{
    __syncthreads();
    if (threadIdx.x == 0) {
        __threadfence();
        unsigned gen = g_gen;
        if (atomicAdd(&g_cnt, 1u) == NBLK - 1u) {
            g_cnt = 0u;
            __threadfence();
            g_gen = gen + 1u;
        } else {
            while (g_gen == gen) { }
            __threadfence();
        }
    }
    __syncthreads();
}

// ---------------------------------------------------------------------------
// cp.async helpers (L1-bypass .cg: L2 is the coherence point for h ping-pong)
// ---------------------------------------------------------------------------
__device__ __forceinline__ void cpa16(void* sdst, const void* gsrc)
{
    unsigned int s = (unsigned int)__cvta_generic_to_shared(sdst);
    asm volatile("cp.async.cg.shared.global [%0], [%1], 16;\n" :: "r"(s), "l"(gsrc));
}

// ---------------------------------------------------------------------------
// Persistent LSTM kernel: 128 blocks = 2 batch-halves x 64 n-blocks.
// Block (mb, nb): batches [mb*64, +64), j-cols [nb*16, +16) x all 4 gates.
// Weights resident in SMEM for all 256 steps; C resident in SMEM.
// ---------------------------------------------------------------------------
__global__ void __launch_bounds__(256)
k_lstm(const int* __restrict__ x)
{
    using namespace nvcuda::wmma;
    extern __shared__ unsigned char smem[];
    __nv_bfloat16* Ws = (__nv_bfloat16*)(smem + WS_OFF);   // [64][WS_STRIDE], n_local = gate*16+jj
    __nv_bfloat16* As = (__nv_bfloat16*)(smem + AS_OFF);   // 2 x [64][AS_STRIDE]
    float*         zs = (float*)(smem + ZS_OFF);           // [64][68]
    float*         Cs = (float*)(smem + CS_OFF);           // [64][16]

    const int bx    = blockIdx.x;
    const int nb    = bx & 63;
    const int mb    = bx >> 6;
    const int mbase = mb * 64;
    const int jb    = nb * 16;
    const int tid   = threadIdx.x;

    // ---- one-time: load weight slice into SMEM, zero C slice ----
    for (int i = tid; i < 64 * 128; i += 256) {            // 8192 uint4
        int r = i >> 7;                                    // n_local row
        int c = i & 127;                                   // uint4 column
        int gate = r >> 4, jj = r & 15;
        const uint4* src = (const uint4*)(g_Whb + (size_t)(gate * 1024 + jb + jj) * H_) + c;
        *((uint4*)(Ws + r * WS_STRIDE) + c) = *src;
    }
    for (int i = tid; i < 64 * 16; i += 256) Cs[i] = 0.f;
    __syncthreads();

    const int w   = tid >> 5;
    const int wm  = w >> 1;          // m-tile 0..3
    const int wn0 = w & 1;           // n-tiles {wn0, wn0+2}

    for (int s = 0; s < S_; s++) {
        const __nv_bfloat16* hb = g_hb[s & 1];

        // stage chunk 0
        {
            const __nv_bfloat16* src = hb + (size_t)mbase * H_;
#pragma unroll
            for (int i = 0; i < 4; i++) {
                int p = tid + i * 256;
                int m = p >> 4, c = p & 15;
                cpa16(As + m * AS_STRIDE + c * 8, src + m * H_ + c * 8);
            }
            asm volatile("cp.async.commit_group;\n" ::: "memory");
        }

        fragment<accumulator, 16, 16, 16, float> acc0, acc1;
        fill_fragment(acc0, 0.f);
        fill_fragment(acc1, 0.f);

        for (int kb = 0; kb < 8; kb++) {
            if (kb < 7) {
                const __nv_bfloat16* src = hb + (size_t)mbase * H_ + (kb + 1) * KC;
                __nv_bfloat16* dst = As + ((kb + 1) & 1) * 64 * AS_STRIDE;
#pragma unroll
                for (int i = 0; i < 4; i++) {
                    int p = tid + i * 256;
                    int m = p >> 4, c = p & 15;
                    cpa16(dst + m * AS_STRIDE + c * 8, src + m * H_ + c * 8);
                }
                asm volatile("cp.async.commit_group;\n" ::: "memory");
                asm volatile("cp.async.wait_group 1;\n" ::: "memory");
            } else {
                asm volatile("cp.async.wait_group 0;\n" ::: "memory");
            }
            __syncthreads();

            const __nv_bfloat16* Ab = As + (kb & 1) * 64 * AS_STRIDE + wm * 16 * AS_STRIDE;
            const __nv_bfloat16* Bb = Ws + kb * KC;
#pragma unroll
            for (int kk = 0; kk < KC; kk += 16) {
                fragment<matrix_a, 16, 16, 16, __nv_bfloat16, row_major> fa;
                load_matrix_sync(fa, Ab + kk, AS_STRIDE);
                fragment<matrix_b, 16, 16, 16, __nv_bfloat16, col_major> fb;
                load_matrix_sync(fb, Bb + (wn0 * 16) * WS_STRIDE + kk, WS_STRIDE);
                mma_sync(acc0, fa, fb, acc0);
                load_matrix_sync(fb, Bb + ((wn0 + 2) * 16) * WS_STRIDE + kk, WS_STRIDE);
                mma_sync(acc1, fa, fb, acc1);
            }
            __syncthreads();
        }

        store_matrix_sync(&zs[(wm * 16) * 68 + wn0 * 16],       acc0, 68, mem_row_major);
        store_matrix_sync(&zs[(wm * 16) * 68 + (wn0 + 2) * 16], acc1, 68, mem_row_major);
        __syncthreads();

        // epilogue: gates + C/h update for this block's 64 batches x 16 j
        __nv_bfloat16* hnext = g_hb[(s & 1) ^ 1];
#pragma unroll
        for (int i = 0; i < 4; i++) {
            int p  = tid + i * 256;
            int m  = p >> 4;
            int jj = p & 15;
            int b  = mbase + m;
            int j  = jb + jj;
            int c  = __ldg(x + b * S_ + s);
            float r = (c > 0) ? 1.f : 0.f;
            const float* tb = g_table + (size_t)c * N4 + j;
            float zf = zs[m * 68 +      jj] + tb[0];
            float zi = zs[m * 68 + 16 + jj] + tb[1024];
            float zg = zs[m * 68 + 32 + jj] + tb[2048];
            float zo = zs[m * 68 + 48 + jj] + tb[3072];
            float fg = 1.f / (1.f + __expf(-zf));
            float ig = 1.f / (1.f + __expf(-zi));
            float gg = 1.f / (1.f + __expf(-zg));     // sigmoid (as in reference)
            float og = 1.f / (1.f + __expf(-zo));
            float C  = (gg * ig + Cs[m * 16 + jj] * fg) * r;
            Cs[m * 16 + jj] = C;
            float h = og * tanhf(C);
            hnext[b * H_ + j] = __float2bfloat16(h);
            if (s == S_ - 1) g_h[b * H_ + j] = h;
        }

        grid_barrier();
    }
}

// ---------------------------------------------------------------------------
// Final projection + log_softmax.
// ---------------------------------------------------------------------------
__global__ void k_final(const float* __restrict__ Wph, const float* __restrict__ bp,
                        float* __restrict__ out)
{
    int b = blockIdx.x;
    int j = threadIdx.x;
    const float* h = g_h + (size_t)b * H_;
    float acc = bp[j];
    for (int k = 0; k < H_; k++)
        acc = fmaf(h[k], Wph[k * NC_ + j], acc);

    __shared__ float red[NC_];
    red[j] = acc;
    __syncthreads();
    for (int off = 64; off > 0; off >>= 1) {
        if (j < off) red[j] = fmaxf(red[j], red[j + off]);
        __syncthreads();
    }
    float m = red[0];
    __syncthreads();
    red[j] = expf(acc - m);
    __syncthreads();
    for (int off = 64; off > 0; off >>= 1) {
        if (j < off) red[j] += red[j + off];
        __syncthreads();
    }
    float lse = m + logf(red[0]);
    out[b * NC_ + j] = acc - lse;
}

// ---------------------------------------------------------------------------
extern "C" void kernel_launch(void* const* d_in, const int* in_sizes, int n_in,
                              void* d_out, int out_size)
{
    const int*   x   = (const int*)  d_in[0];
    const float* emb = (const float*)d_in[1];
    const float* Wfx = (const float*)d_in[2];
    const float* Wfh = (const float*)d_in[3];
    const float* bf  = (const float*)d_in[4];
    const float* Wix = (const float*)d_in[5];
    const float* Wih = (const float*)d_in[6];
    const float* bi  = (const float*)d_in[7];
    const float* Wgx = (const float*)d_in[8];
    const float* Wgh = (const float*)d_in[9];
    const float* bg  = (const float*)d_in[10];
    const float* Wox = (const float*)d_in[11];
    const float* Woh = (const float*)d_in[12];
    const float* bo  = (const float*)d_in[13];
    const float* Wph = (const float*)d_in[14];
    const float* bp  = (const float*)d_in[15];
    float* out = (float*)d_out;

    cudaFuncSetAttribute(k_lstm, cudaFuncAttributeMaxDynamicSharedMemorySize, SMEM_TOTAL);

    k_table<<<dim3(16, 17), 256>>>(emb, Wfx, Wix, Wgx, Wox, bf, bi, bg, bo);
    k_convert<<<dim3(32, 32, 4), dim3(32, 8)>>>(Wfh, Wih, Wgh, Woh);
    k_init<<<(B_ * H_ + 255) / 256, 256>>>();

    k_lstm<<<NBLK, 256, SMEM_TOTAL>>>(x);

    k_final<<<NC_, NC_>>>(Wph, bp, out);
}